// round 16
// baseline (speedup 1.0000x reference)
#include <cuda_runtime.h>

// ---------------------------------------------------------------------------
// MCA linear attention, fp32, FFMA2 register-tiled GEMMs.
// R15: pass2 rebuilt on 128-px tiles with 8 rows x 4 px thread tiles on all
//      256 threads (smem traffic 4 -> 3 B/FFMA2) and sQ aliased onto sXh
//      (fits 2 blocks/SM). pass1 = R14 (winning version).
// ---------------------------------------------------------------------------

#define DINL __device__ __forceinline__
typedef unsigned long long u64;

namespace mca {

constexpr int Bn = 8;
constexpr int Np = 25600;
constexpr int TPB = 256;
constexpr int GRID = 296;           // 2 blocks per SM
// pass1 tiling
constexpr int TILE1 = 64;
constexpr int T1_TOTAL = 3200;      // Bn*Np/TILE1
constexpr int T1_BATCH = 400;
constexpr int XP1 = 66;             // u64 pitch (64 px)
constexpr int KP = 68;              // f32 pitch for k/v staging (u64 pitch 34)
// pass2 tiling
constexpr int TILE2 = 128;
constexpr int T2_TOTAL = 1600;      // Bn*Np/TILE2
constexpr int T2_BATCH = 200;
constexpr int XP2 = 130;            // u64 pitch (128 px)
constexpr float EPSV = 1e-6f;

__device__ float g_attn[Bn * 64 * 8];   // [b][pm][c]  (atomic accum)
__device__ float g_ksum_raw[Bn * 64];
__device__ float g_ksum[Bn * 64];       // +eps
__device__ float g_W2[Bn * 4096];       // dense packed; u64 view: [b*2048 + k2*64 + o]

DINL u64 pk2(float lo, float hi) {
    u64 r; asm("mov.b64 %0, {%1, %2};" : "=l"(r) : "f"(lo), "f"(hi)); return r;
}
DINL void upk2(u64 v, float& lo, float& hi) {
    asm("mov.b64 {%0, %1}, %2;" : "=f"(lo), "=f"(hi) : "l"(v));
}
DINL u64 ffma2(u64 a, u64 b, u64 c) {
    u64 d; asm("fma.rn.f32x2 %0, %1, %2, %3;" : "=l"(d) : "l"(a), "l"(b), "l"(c));
    return d;
}
DINL u64 fadd2(u64 a, u64 b) {
    u64 d; asm("add.rn.f32x2 %0, %1, %2;" : "=l"(d) : "l"(a), "l"(b));
    return d;
}
DINL u64 fmul2(u64 a, u64 b) {
    u64 d; asm("mul.rn.f32x2 %0, %1, %2;" : "=l"(d) : "l"(a), "l"(b));
    return d;
}
// Fast stable softplus: arg of __logf is in (1,2], no overflow anywhere.
DINL float softplus(float x) {
    float e = __expf(-fabsf(x));
    return fmaxf(x, 0.0f) + __logf(1.0f + e);
}

// ---------------------------------------------------------------------------
__global__ void zero_scratch() {
    int i = blockIdx.x * blockDim.x + threadIdx.x;
    int stride = gridDim.x * blockDim.x;
    for (int j = i; j < Bn * 64 * 8; j += stride) g_attn[j] = 0.0f;
    for (int j = i; j < Bn * 64; j += stride) g_ksum_raw[j] = 0.0f;
}

// ---------------------------------------------------------------------------
// pass1 (R14): smem sW[4096] sX0[2112] sX1[2112] u64, sKV[128*68] f32
// (aliased by sRed during flush), sb[128].  ~102KB -> 2 blocks/SM.
// ---------------------------------------------------------------------------
__global__ __launch_bounds__(TPB, 2)
void pass1(const float* __restrict__ low,
           const float* __restrict__ wk, const float* __restrict__ bk,
           const float* __restrict__ wv, const float* __restrict__ bv) {
    extern __shared__ u64 smu[];
    u64*   sW  = smu;                          // 4096
    u64*   sX0 = smu + 4096;                   // 2112
    u64*   sX1 = smu + 4096 + 2112;            // 2112
    float* sKV = (float*)(smu + 4096 + 4224);  // 128*KP
    float* sb  = sKV + 128 * KP;               // 128
    float* sRed = sKV;                         // alias (flush only; sKV dead then)

    const int tid = threadIdx.x;
    const int blk = blockIdx.x;
    const int t0 = (int)(((long long)blk * T1_TOTAL) / GRID);
    const int t1 = (int)(((long long)(blk + 1) * T1_TOTAL) / GRID);

    for (int i = tid; i < 4096; i += TPB) {
        int k2 = i >> 7, r = i & 127;
        const float* Wr = (r < 64) ? (wk + r * 64) : (wv + (r - 64) * 64);
        sW[k2 * 128 + r] = pk2(Wr[2 * k2], Wr[2 * k2 + 1]);
    }
    if (tid < 64) sb[tid] = bk[tid];
    else if (tid < 128) sb[tid] = bv[tid - 64];

    // prologue: stage tile t0 into buf[t0&1]
    {
        const int bb = t0 / T1_BATCH;
        const int n00 = (t0 % T1_BATCH) * TILE1;
        const float* xb = low + ((size_t)bb * 64) * Np + n00;
        u64* sXc = (t0 & 1) ? sX1 : sX0;
#pragma unroll
        for (int it = 0; it < 8; it++) {
            int idx = tid + TPB * it;
            int k2 = idx >> 6, px = idx & 63;
            sXc[k2 * XP1 + px] =
                pk2(xb[(size_t)(2 * k2) * Np + px], xb[(size_t)(2 * k2 + 1) * Np + px]);
        }
    }

    const int ocg = tid >> 4;          // 0..15
    const int r0  = ocg * 8;
    const int pg  = tid & 15;
    const bool isK = (r0 < 64);

    const int pm = tid & 63, slice = tid >> 6, p8 = pm & 56;
    u64 racc2[8] = {0, 0, 0, 0, 0, 0, 0, 0};
    u64 rks2 = 0ull;
    int bprev = t0 / T1_BATCH;

#define P1_FLUSH(BIDX)                                                        \
    do {                                                                      \
        __syncthreads();                                                      \
        _Pragma("unroll")                                                     \
        for (int c = 0; c < 8; c++) {                                         \
            float lo, hi; upk2(racc2[c], lo, hi);                             \
            sRed[tid * 9 + c] = lo + hi;                                      \
        }                                                                     \
        { float lo, hi; upk2(rks2, lo, hi); sRed[tid * 9 + 8] = lo + hi; }    \
        __syncthreads();                                                      \
        if (tid < 64) {                                                       \
            float s[9] = {0, 0, 0, 0, 0, 0, 0, 0, 0};                         \
            _Pragma("unroll")                                                 \
            for (int sl = 0; sl < 4; sl++) {                                  \
                const float* p = sRed + (sl * 64 + tid) * 9;                  \
                _Pragma("unroll")                                             \
                for (int c = 0; c < 9; c++) s[c] += p[c];                     \
            }                                                                 \
            _Pragma("unroll")                                                 \
            for (int c = 0; c < 8; c++)                                       \
                atomicAdd(g_attn + ((BIDX) * 64 + tid) * 8 + c, s[c]);        \
            atomicAdd(g_ksum_raw + (BIDX) * 64 + tid, s[8]);                  \
        }                                                                     \
        _Pragma("unroll")                                                     \
        for (int c = 0; c < 8; c++) racc2[c] = 0ull;                          \
        rks2 = 0ull;                                                          \
    } while (0)

    for (int t = t0; t < t1; ++t) {
        const int b = t / T1_BATCH;
        if (b != bprev) { P1_FLUSH(bprev); bprev = b; }

        __syncthreads();   // staged buf visible; sKV free (prev stage-B done)
        u64* sXc = (t & 1) ? sX1 : sX0;
        u64* sXn = (t & 1) ? sX0 : sX1;

        u64 acc[32];
#pragma unroll
        for (int i = 0; i < 32; i++) acc[i] = 0ull;
#pragma unroll 4
        for (int k2 = 0; k2 < 32; k2++) {
            const ulonglong2* wp = (const ulonglong2*)(sW + k2 * 128 + r0);
            ulonglong2 w01 = wp[0], w23 = wp[1], w45 = wp[2], w67 = wp[3];
            u64 w2r[8] = {w01.x, w01.y, w23.x, w23.y, w45.x, w45.y, w67.x, w67.y};
            ulonglong2 xa = *(const ulonglong2*)(sXc + k2 * XP1 + 2 * pg);
            ulonglong2 xc = *(const ulonglong2*)(sXc + k2 * XP1 + 32 + 2 * pg);
            u64 x2r[4] = {xa.x, xa.y, xc.x, xc.y};
#pragma unroll
            for (int oi = 0; oi < 8; oi++)
#pragma unroll
                for (int j = 0; j < 4; j++)
                    acc[oi * 4 + j] = ffma2(w2r[oi], x2r[j], acc[oi * 4 + j]);
        }

        const bool pfv = (t + 1 < t1);
        u64 pf[8];
        if (pfv) {
            const int t2 = t + 1;
            const int b2 = t2 / T1_BATCH;
            const int n2 = (t2 % T1_BATCH) * TILE1;
            const float* xb2 = low + ((size_t)b2 * 64) * Np + n2;
#pragma unroll
            for (int it = 0; it < 8; it++) {
                int idx = tid + TPB * it;
                int k2 = idx >> 6, px = idx & 63;
                pf[it] = pk2(xb2[(size_t)(2 * k2) * Np + px],
                             xb2[(size_t)(2 * k2 + 1) * Np + px]);
            }
        }

#pragma unroll
        for (int oi = 0; oi < 8; oi++) {
            const int r = r0 + oi;
            const float bias = sb[r];
#pragma unroll
            for (int jj = 0; jj < 2; jj++) {
                float lo0, hi0, lo1, hi1;
                upk2(acc[oi * 4 + 2 * jj], lo0, hi0);
                upk2(acc[oi * 4 + 2 * jj + 1], lo1, hi1);
                float v0 = lo0 + hi0 + bias;
                float v1 = lo1 + hi1 + bias;
                if (isK) { v0 = softplus(v0); v1 = softplus(v1); }
                *(u64*)(sKV + r * KP + 2 * pg + 32 * jj) = pk2(v0, v1);
            }
        }

        if (pfv) {
#pragma unroll
            for (int it = 0; it < 8; it++) {
                int idx = tid + TPB * it;
                int k2 = idx >> 6, px = idx & 63;
                sXn[k2 * XP1 + px] = pf[it];
            }
        }
        __syncthreads();   // sKV visible; STS(next tile) drained

        const u64* kr = (const u64*)sKV + pm * 34 + slice * 8;
        const u64* vr = (const u64*)sKV + (64 + p8) * 34 + slice * 8;
#pragma unroll
        for (int ii = 0; ii < 4; ii++) {
            ulonglong2 kq = *(const ulonglong2*)(kr + 2 * ii);
            rks2 = fadd2(rks2, kq.x);
            rks2 = fadd2(rks2, kq.y);
#pragma unroll
            for (int c = 0; c < 8; c++) {
                ulonglong2 vq = *(const ulonglong2*)(vr + c * 34 + 2 * ii);
                racc2[c] = ffma2(kq.x, vq.x, racc2[c]);
                racc2[c] = ffma2(kq.y, vq.y, racc2[c]);
            }
        }
    }
    P1_FLUSH(bprev);
#undef P1_FLUSH
}

// ---------------------------------------------------------------------------
__global__ __launch_bounds__(512, 1)
void prep(const float* __restrict__ wo) {
    __shared__ float sA[512];
    const int tid = threadIdx.x;
    const int b = blockIdx.x;
    sA[tid] = g_attn[b * 512 + tid];
    if (tid < 64) g_ksum[b * 64 + tid] = g_ksum_raw[b * 64 + tid] + EPSV;
    __syncthreads();
    for (int idx = tid; idx < 4096; idx += 512) {
        int o = idx >> 6, pm = idx & 63;
        const float* wr = wo + o * 64 + (pm & 56);
        const float* ar = sA + pm * 8;
        float acc = 0.0f;
#pragma unroll
        for (int c = 0; c < 8; c++) acc += wr[c] * ar[c];
        g_W2[b * 4096 + ((pm >> 1) * 64 + o) * 2 + (pm & 1)] = acc;
    }
}

// ---------------------------------------------------------------------------
// pass2 (R15): 128-px tiles. smem (u64):
//   sWq [2048] sW2 [2048] sXh [4160] sXl [4160] sks2[32] + biases
//   sQ ALIASES sXh (valid: barrier after GEMM1 k-loop retires all X reads).
//   total ~100KB -> 2 blocks/SM.
// GEMM thread tile: 8 rows x 4 px on all 256 threads (64 rows x 128 px).
// ---------------------------------------------------------------------------
__global__ __launch_bounds__(TPB, 2)
void pass2(const float* __restrict__ high, const float* __restrict__ low,
           const float* __restrict__ wqh, const float* __restrict__ bqh,
           const float* __restrict__ wql, const float* __restrict__ bql,
           const float* __restrict__ bo, float* __restrict__ out) {
    extern __shared__ u64 smu[];
    u64*   sWq  = smu;                         // 2048
    u64*   sW2  = smu + 2048;                  // 2048
    u64*   sXh  = smu + 4096;                  // 4160
    u64*   sXl  = smu + 4096 + 4160;           // 4160
    u64*   sQ   = sXh;                         // ALIAS (post-GEMM1 only)
    u64*   sks2 = smu + 4096 + 2 * 4160;       // 32
    float* sbq  = (float*)(sks2 + 32);         // 64
    float* sbo  = sbq + 64;                    // 64

    const int tid = threadIdx.x;
    const int blk = blockIdx.x;
    const int t0 = (int)(((long long)blk * T2_TOTAL) / GRID);
    const int t1 = (int)(((long long)(blk + 1) * T2_TOTAL) / GRID);

    for (int i = tid; i < 2048; i += TPB) {
        int k2 = i >> 6, r = i & 63;
        const float* Wr = (r < 32) ? (wqh + r * 64) : (wql + (r - 32) * 64);
        sWq[k2 * 64 + r] = pk2(Wr[2 * k2], Wr[2 * k2 + 1]);
    }
    if (tid < 32) sbq[tid] = bqh[tid];
    else if (tid < 64) sbq[tid] = bql[tid - 32];
    else if (tid < 128) sbo[tid - 64] = bo[tid - 64];

    // GEMM coords (all 256 threads): 8 rows x 4 px over 64 rows x 128 px
    const int rG = (tid >> 5) * 8;           // 0,8,...,56 (uniform per warp)
    const int pg = tid & 31;                 // px = {2pg,2pg+1, 64+2pg,64+2pg+1}

    int bprev = -1;

    for (int t = t0; t < t1; ++t) {
        const int b = t / T2_BATCH;
        if (b != bprev) {
            __syncthreads();   // prior GEMM2/norm readers of sW2/sks2 done
            const u64* gW2 = (const u64*)g_W2 + (size_t)b * 2048;
            for (int i = tid; i < 2048; i += TPB) sW2[i] = gW2[i];
            if (tid < 32)
                sks2[tid] = pk2(g_ksum[b * 64 + 2 * tid], g_ksum[b * 64 + 2 * tid + 1]);
            bprev = b;
        }
        const int n0 = (t % T2_BATCH) * TILE2;
        const float* xh = high + ((size_t)b * 64) * Np + n0;
        const float* xl = low  + ((size_t)b * 64) * Np + n0;

        __syncthreads();   // prev GEMM2 done reading sQ(=sXh) and sW2
#pragma unroll
        for (int it = 0; it < 16; it++) {
            int idx = tid + TPB * it;          // 0..4095
            int k2 = idx >> 7, px = idx & 127;
            sXh[k2 * XP2 + px] =
                pk2(xh[(size_t)(2 * k2) * Np + px], xh[(size_t)(2 * k2 + 1) * Np + px]);
            sXl[k2 * XP2 + px] =
                pk2(xl[(size_t)(2 * k2) * Np + px], xl[(size_t)(2 * k2 + 1) * Np + px]);
        }
        __syncthreads();

        // ---- GEMM1 k-loop: raw q = Wq @ X (8 rows x 4 px per thread) ----
        u64 acc[32];
#pragma unroll
        for (int i = 0; i < 32; i++) acc[i] = 0ull;
        {
            const u64* sXin = (rG < 32) ? sXh : sXl;
#pragma unroll 4
            for (int k2 = 0; k2 < 32; k2++) {
                const ulonglong2* wp = (const ulonglong2*)(sWq + k2 * 64 + rG);
                ulonglong2 w01 = wp[0], w23 = wp[1], w45 = wp[2], w67 = wp[3];
                u64 w2r[8] = {w01.x, w01.y, w23.x, w23.y, w45.x, w45.y, w67.x, w67.y};
                ulonglong2 xa = *(const ulonglong2*)(sXin + k2 * XP2 + 2 * pg);
                ulonglong2 xc = *(const ulonglong2*)(sXin + k2 * XP2 + 64 + 2 * pg);
                u64 x2r[4] = {xa.x, xa.y, xc.x, xc.y};
#pragma unroll
                for (int oi = 0; oi < 8; oi++)
#pragma unroll
                    for (int j = 0; j < 4; j++)
                        acc[oi * 4 + j] = ffma2(w2r[oi], x2r[j], acc[oi * 4 + j]);
            }
        }
        __syncthreads();   // ALL X reads retired -> sXh reusable as sQ

        // ---- epilogue: bias + softplus, pack row-pairs into sQ (=sXh) ----
#pragma unroll
        for (int oi2 = 0; oi2 < 4; oi2++) {
            const int ra = rG + 2 * oi2;
            const float ba0 = sbq[ra], ba1 = sbq[ra + 1];
#pragma unroll
            for (int jj = 0; jj < 2; jj++) {
                float lo, hi;
                upk2(acc[(2 * oi2) * 4 + 2 * jj], lo, hi);
                float v00 = softplus(lo + hi + ba0);
                upk2(acc[(2 * oi2) * 4 + 2 * jj + 1], lo, hi);
                float v01 = softplus(lo + hi + ba0);
                upk2(acc[(2 * oi2 + 1) * 4 + 2 * jj], lo, hi);
                float v10 = softplus(lo + hi + ba1);
                upk2(acc[(2 * oi2 + 1) * 4 + 2 * jj + 1], lo, hi);
                float v11 = softplus(lo + hi + ba1);
                ulonglong2 st;
                st.x = pk2(v00, v10);
                st.y = pk2(v01, v11);
                *(ulonglong2*)(sQ + (ra >> 1) * XP2 + 64 * jj + 2 * pg) = st;
            }
        }
        __syncthreads();

        // ---- fused norm + in-place rescale: 8 heads x 128 px ----
#pragma unroll
        for (int rr = 0; rr < 4; rr++) {
            int it = tid + TPB * rr;           // 0..1023
            int h = it >> 7, px = it & 127;
            u64 q0 = sQ[(h * 4 + 0) * XP2 + px];
            u64 q1 = sQ[(h * 4 + 1) * XP2 + px];
            u64 q2 = sQ[(h * 4 + 2) * XP2 + px];
            u64 q3 = sQ[(h * 4 + 3) * XP2 + px];
            u64 a = ffma2(q0, sks2[h * 4 + 0], 0ull);
            a = ffma2(q1, sks2[h * 4 + 1], a);
            a = ffma2(q2, sks2[h * 4 + 2], a);
            a = ffma2(q3, sks2[h * 4 + 3], a);
            float lo, hi; upk2(a, lo, hi);
            float inv = 1.0f / (lo + hi);
            u64 iv = pk2(inv, inv);
            sQ[(h * 4 + 0) * XP2 + px] = fmul2(q0, iv);
            sQ[(h * 4 + 1) * XP2 + px] = fmul2(q1, iv);
            sQ[(h * 4 + 2) * XP2 + px] = fmul2(q2, iv);
            sQ[(h * 4 + 3) * XP2 + px] = fmul2(q3, iv);
        }
        __syncthreads();

        // ---- GEMM2: out = W2 @ q' + bo (8 rows x 4 px per thread) ----
        {
#pragma unroll
            for (int i = 0; i < 32; i++) acc[i] = 0ull;
#pragma unroll 4
            for (int k2 = 0; k2 < 32; k2++) {
                const ulonglong2* wp = (const ulonglong2*)(sW2 + k2 * 64 + rG);
                ulonglong2 w01 = wp[0], w23 = wp[1], w45 = wp[2], w67 = wp[3];
                u64 w2r[8] = {w01.x, w01.y, w23.x, w23.y, w45.x, w45.y, w67.x, w67.y};
                ulonglong2 xa = *(const ulonglong2*)(sQ + k2 * XP2 + 2 * pg);
                ulonglong2 xc = *(const ulonglong2*)(sQ + k2 * XP2 + 64 + 2 * pg);
                u64 x2r[4] = {xa.x, xa.y, xc.x, xc.y};
#pragma unroll
                for (int oi = 0; oi < 8; oi++)
#pragma unroll
                    for (int j = 0; j < 4; j++)
                        acc[oi * 4 + j] = ffma2(w2r[oi], x2r[j], acc[oi * 4 + j]);
            }
            float* ob = out + ((size_t)b * 64) * Np + n0;
#pragma unroll
            for (int oi = 0; oi < 8; oi++) {
                const int r = rG + oi;
                const float bias = sbo[r];
#pragma unroll
                for (int jj = 0; jj < 2; jj++) {
                    float lo0, hi0, lo1, hi1;
                    upk2(acc[oi * 4 + 2 * jj], lo0, hi0);
                    upk2(acc[oi * 4 + 2 * jj + 1], lo1, hi1);
                    *(float2*)(ob + (size_t)r * Np + 64 * jj + 2 * pg) =
                        make_float2(lo0 + hi0 + bias, lo1 + hi1 + bias);
                }
            }
        }
    }
}

constexpr int SMEM1 = (4096 + 2 * 2112) * 8 + (128 * KP + 128) * 4;   // 101,888
constexpr int SMEM2 = (4096 + 2 * 4160 + 32) * 8 + 128 * 4;           // 100,096

}  // namespace mca

// ---------------------------------------------------------------------------
extern "C" void kernel_launch(void* const* d_in, const int* in_sizes, int n_in,
                              void* d_out, int out_size) {
    using namespace mca;
    (void)in_sizes; (void)n_in; (void)out_size;

    const float* high = (const float*)d_in[0];
    const float* low  = (const float*)d_in[1];
    const float* wqh  = (const float*)d_in[2];
    const float* bqh  = (const float*)d_in[3];
    const float* wql  = (const float*)d_in[4];
    const float* bql  = (const float*)d_in[5];
    const float* wk   = (const float*)d_in[6];
    const float* bk   = (const float*)d_in[7];
    const float* wv   = (const float*)d_in[8];
    const float* bv   = (const float*)d_in[9];
    const float* wo   = (const float*)d_in[10];
    const float* bo   = (const float*)d_in[11];
    float* out = (float*)d_out;

    cudaFuncSetAttribute(pass1, cudaFuncAttributeMaxDynamicSharedMemorySize, SMEM1);
    cudaFuncSetAttribute(pass2, cudaFuncAttributeMaxDynamicSharedMemorySize, SMEM2);

    zero_scratch<<<8, 512>>>();
    pass1<<<GRID, TPB, SMEM1>>>(low, wk, bk, wv, bv);
    prep<<<Bn, 512>>>(wo);
    pass2<<<GRID, TPB, SMEM2>>>(high, low, wqh, bqh, wql, bql, bo, out);
}

// round 17
// speedup vs baseline: 1.0249x; 1.0249x over previous
#include <cuda_runtime.h>

// ---------------------------------------------------------------------------
// MCA linear attention, fp32, FFMA2 register-tiled GEMMs.
// R17: R14 base. pass2 thread tile -> 8 rows x 2 px on all 256 threads
//      (x-traffic 2 -> 1 B/FFMA2, weights warp-uniform broadcast, acc 32 regs
//      so no spills). pass1 = R14 (winning version).
// ---------------------------------------------------------------------------

#define DINL __device__ __forceinline__
typedef unsigned long long u64;

namespace mca {

constexpr int Bn = 8;
constexpr int Np = 25600;
constexpr int TILE = 64;            // pixels per tile
constexpr int TPB = 256;
constexpr int GRID = 296;           // 2 blocks per SM
constexpr int TILES_TOTAL = 3200;   // Bn*Np/TILE
constexpr int TPBATCH = 400;        // tiles per batch
constexpr int XP = 66;              // u64 pitch for packed activations (64 px)
constexpr int KP = 68;              // f32 pitch for k/v staging (u64 pitch 34)
constexpr float EPSV = 1e-6f;

__device__ float g_attn[Bn * 64 * 8];   // [b][pm][c]  (atomic accum)
__device__ float g_ksum_raw[Bn * 64];
__device__ float g_ksum[Bn * 64];       // +eps
__device__ float g_W2[Bn * 4096];       // dense packed; u64 view: [b*2048 + k2*64 + o]

DINL u64 pk2(float lo, float hi) {
    u64 r; asm("mov.b64 %0, {%1, %2};" : "=l"(r) : "f"(lo), "f"(hi)); return r;
}
DINL void upk2(u64 v, float& lo, float& hi) {
    asm("mov.b64 {%0, %1}, %2;" : "=f"(lo), "=f"(hi) : "l"(v));
}
DINL u64 ffma2(u64 a, u64 b, u64 c) {
    u64 d; asm("fma.rn.f32x2 %0, %1, %2, %3;" : "=l"(d) : "l"(a), "l"(b), "l"(c));
    return d;
}
DINL u64 fadd2(u64 a, u64 b) {
    u64 d; asm("add.rn.f32x2 %0, %1, %2;" : "=l"(d) : "l"(a), "l"(b));
    return d;
}
DINL u64 fmul2(u64 a, u64 b) {
    u64 d; asm("mul.rn.f32x2 %0, %1, %2;" : "=l"(d) : "l"(a), "l"(b));
    return d;
}
// Fast stable softplus: arg of __logf is in (1,2], no overflow anywhere.
DINL float softplus(float x) {
    float e = __expf(-fabsf(x));
    return fmaxf(x, 0.0f) + __logf(1.0f + e);
}

// ---------------------------------------------------------------------------
__global__ void zero_scratch() {
    int i = blockIdx.x * blockDim.x + threadIdx.x;
    int stride = gridDim.x * blockDim.x;
    for (int j = i; j < Bn * 64 * 8; j += stride) g_attn[j] = 0.0f;
    for (int j = i; j < Bn * 64; j += stride) g_ksum_raw[j] = 0.0f;
}

// ---------------------------------------------------------------------------
// pass1 (R14): smem sW[4096] sX0[2112] sX1[2112] u64, sKV[128*68] f32
// (aliased by sRed during flush), sb[128].  ~102KB -> 2 blocks/SM.
// ---------------------------------------------------------------------------
__global__ __launch_bounds__(TPB, 2)
void pass1(const float* __restrict__ low,
           const float* __restrict__ wk, const float* __restrict__ bk,
           const float* __restrict__ wv, const float* __restrict__ bv) {
    extern __shared__ u64 smu[];
    u64*   sW  = smu;                          // 4096
    u64*   sX0 = smu + 4096;                   // 2112
    u64*   sX1 = smu + 4096 + 2112;            // 2112
    float* sKV = (float*)(smu + 4096 + 4224);  // 128*KP
    float* sb  = sKV + 128 * KP;               // 128
    float* sRed = sKV;                         // alias (flush only; sKV dead then)

    const int tid = threadIdx.x;
    const int blk = blockIdx.x;
    const int t0 = (int)(((long long)blk * TILES_TOTAL) / GRID);
    const int t1 = (int)(((long long)(blk + 1) * TILES_TOTAL) / GRID);

    for (int i = tid; i < 4096; i += TPB) {
        int k2 = i >> 7, r = i & 127;
        const float* Wr = (r < 64) ? (wk + r * 64) : (wv + (r - 64) * 64);
        sW[k2 * 128 + r] = pk2(Wr[2 * k2], Wr[2 * k2 + 1]);
    }
    if (tid < 64) sb[tid] = bk[tid];
    else if (tid < 128) sb[tid] = bv[tid - 64];

    // prologue: stage tile t0 into buf[t0&1]
    {
        const int bb = t0 / TPBATCH;
        const int n00 = (t0 % TPBATCH) * TILE;
        const float* xb = low + ((size_t)bb * 64) * Np + n00;
        u64* sXc = (t0 & 1) ? sX1 : sX0;
#pragma unroll
        for (int it = 0; it < 8; it++) {
            int idx = tid + TPB * it;
            int k2 = idx >> 6, px = idx & 63;
            sXc[k2 * XP + px] =
                pk2(xb[(size_t)(2 * k2) * Np + px], xb[(size_t)(2 * k2 + 1) * Np + px]);
        }
    }

    const int ocg = tid >> 4;          // 0..15
    const int r0  = ocg * 8;
    const int pg  = tid & 15;
    const bool isK = (r0 < 64);

    const int pm = tid & 63, slice = tid >> 6, p8 = pm & 56;
    u64 racc2[8] = {0, 0, 0, 0, 0, 0, 0, 0};
    u64 rks2 = 0ull;
    int bprev = t0 / TPBATCH;

#define P1_FLUSH(BIDX)                                                        \
    do {                                                                      \
        __syncthreads();                                                      \
        _Pragma("unroll")                                                     \
        for (int c = 0; c < 8; c++) {                                         \
            float lo, hi; upk2(racc2[c], lo, hi);                             \
            sRed[tid * 9 + c] = lo + hi;                                      \
        }                                                                     \
        { float lo, hi; upk2(rks2, lo, hi); sRed[tid * 9 + 8] = lo + hi; }    \
        __syncthreads();                                                      \
        if (tid < 64) {                                                       \
            float s[9] = {0, 0, 0, 0, 0, 0, 0, 0, 0};                         \
            _Pragma("unroll")                                                 \
            for (int sl = 0; sl < 4; sl++) {                                  \
                const float* p = sRed + (sl * 64 + tid) * 9;                  \
                _Pragma("unroll")                                             \
                for (int c = 0; c < 9; c++) s[c] += p[c];                     \
            }                                                                 \
            _Pragma("unroll")                                                 \
            for (int c = 0; c < 8; c++)                                       \
                atomicAdd(g_attn + ((BIDX) * 64 + tid) * 8 + c, s[c]);        \
            atomicAdd(g_ksum_raw + (BIDX) * 64 + tid, s[8]);                  \
        }                                                                     \
        _Pragma("unroll")                                                     \
        for (int c = 0; c < 8; c++) racc2[c] = 0ull;                          \
        rks2 = 0ull;                                                          \
    } while (0)

    for (int t = t0; t < t1; ++t) {
        const int b = t / TPBATCH;
        if (b != bprev) { P1_FLUSH(bprev); bprev = b; }

        __syncthreads();   // staged buf visible; sKV free (prev stage-B done)
        u64* sXc = (t & 1) ? sX1 : sX0;
        u64* sXn = (t & 1) ? sX0 : sX1;

        u64 acc[32];
#pragma unroll
        for (int i = 0; i < 32; i++) acc[i] = 0ull;
#pragma unroll 4
        for (int k2 = 0; k2 < 32; k2++) {
            const ulonglong2* wp = (const ulonglong2*)(sW + k2 * 128 + r0);
            ulonglong2 w01 = wp[0], w23 = wp[1], w45 = wp[2], w67 = wp[3];
            u64 w2r[8] = {w01.x, w01.y, w23.x, w23.y, w45.x, w45.y, w67.x, w67.y};
            ulonglong2 xa = *(const ulonglong2*)(sXc + k2 * XP + 2 * pg);
            ulonglong2 xc = *(const ulonglong2*)(sXc + k2 * XP + 32 + 2 * pg);
            u64 x2r[4] = {xa.x, xa.y, xc.x, xc.y};
#pragma unroll
            for (int oi = 0; oi < 8; oi++)
#pragma unroll
                for (int j = 0; j < 4; j++)
                    acc[oi * 4 + j] = ffma2(w2r[oi], x2r[j], acc[oi * 4 + j]);
        }

        const bool pfv = (t + 1 < t1);
        u64 pf[8];
        if (pfv) {
            const int t2 = t + 1;
            const int b2 = t2 / TPBATCH;
            const int n2 = (t2 % TPBATCH) * TILE;
            const float* xb2 = low + ((size_t)b2 * 64) * Np + n2;
#pragma unroll
            for (int it = 0; it < 8; it++) {
                int idx = tid + TPB * it;
                int k2 = idx >> 6, px = idx & 63;
                pf[it] = pk2(xb2[(size_t)(2 * k2) * Np + px],
                             xb2[(size_t)(2 * k2 + 1) * Np + px]);
            }
        }

#pragma unroll
        for (int oi = 0; oi < 8; oi++) {
            const int r = r0 + oi;
            const float bias = sb[r];
#pragma unroll
            for (int jj = 0; jj < 2; jj++) {
                float lo0, hi0, lo1, hi1;
                upk2(acc[oi * 4 + 2 * jj], lo0, hi0);
                upk2(acc[oi * 4 + 2 * jj + 1], lo1, hi1);
                float v0 = lo0 + hi0 + bias;
                float v1 = lo1 + hi1 + bias;
                if (isK) { v0 = softplus(v0); v1 = softplus(v1); }
                *(u64*)(sKV + r * KP + 2 * pg + 32 * jj) = pk2(v0, v1);
            }
        }

        if (pfv) {
#pragma unroll
            for (int it = 0; it < 8; it++) {
                int idx = tid + TPB * it;
                int k2 = idx >> 6, px = idx & 63;
                sXn[k2 * XP + px] = pf[it];
            }
        }
        __syncthreads();   // sKV visible; STS(next tile) drained

        const u64* kr = (const u64*)sKV + pm * 34 + slice * 8;
        const u64* vr = (const u64*)sKV + (64 + p8) * 34 + slice * 8;
#pragma unroll
        for (int ii = 0; ii < 4; ii++) {
            ulonglong2 kq = *(const ulonglong2*)(kr + 2 * ii);
            rks2 = fadd2(rks2, kq.x);
            rks2 = fadd2(rks2, kq.y);
#pragma unroll
            for (int c = 0; c < 8; c++) {
                ulonglong2 vq = *(const ulonglong2*)(vr + c * 34 + 2 * ii);
                racc2[c] = ffma2(kq.x, vq.x, racc2[c]);
                racc2[c] = ffma2(kq.y, vq.y, racc2[c]);
            }
        }
    }
    P1_FLUSH(bprev);
#undef P1_FLUSH
}

// ---------------------------------------------------------------------------
__global__ __launch_bounds__(512, 1)
void prep(const float* __restrict__ wo) {
    __shared__ float sA[512];
    const int tid = threadIdx.x;
    const int b = blockIdx.x;
    sA[tid] = g_attn[b * 512 + tid];
    if (tid < 64) g_ksum[b * 64 + tid] = g_ksum_raw[b * 64 + tid] + EPSV;
    __syncthreads();
    for (int idx = tid; idx < 4096; idx += 512) {
        int o = idx >> 6, pm = idx & 63;
        const float* wr = wo + o * 64 + (pm & 56);
        const float* ar = sA + pm * 8;
        float acc = 0.0f;
#pragma unroll
        for (int c = 0; c < 8; c++) acc += wr[c] * ar[c];
        g_W2[b * 4096 + ((pm >> 1) * 64 + o) * 2 + (pm & 1)] = acc;
    }
}

// ---------------------------------------------------------------------------
// pass2 (R17): ~84KB smem, 2 blocks/SM. GEMMs on all 256 threads at
// 8 rows x 2 px: rG=(tid>>5)*8 (warp-uniform weights), pg=tid&31.
// x-traffic 1 B/FFMA2; acc[16] u64 = 32 regs (no spills).
// ---------------------------------------------------------------------------
__global__ __launch_bounds__(TPB, 2)
void pass2(const float* __restrict__ high, const float* __restrict__ low,
           const float* __restrict__ wqh, const float* __restrict__ bqh,
           const float* __restrict__ wql, const float* __restrict__ bql,
           const float* __restrict__ bo, float* __restrict__ out) {
    extern __shared__ u64 smu[];
    u64*   sWq  = smu;                         // 2048
    u64*   sW2  = smu + 2048;                  // 2048
    u64*   sXh  = smu + 4096;                  // 2112
    u64*   sXl  = smu + 4096 + 2112;           // 2112
    u64*   sQ   = smu + 4096 + 2 * 2112;       // 2112
    u64*   sks2 = smu + 4096 + 3 * 2112;       // 32
    float* sbq  = (float*)(sks2 + 32);         // 64
    float* sbo  = sbq + 64;                    // 64

    const int tid = threadIdx.x;
    const int blk = blockIdx.x;
    const int t0 = (int)(((long long)blk * TILES_TOTAL) / GRID);
    const int t1 = (int)(((long long)(blk + 1) * TILES_TOTAL) / GRID);

    for (int i = tid; i < 2048; i += TPB) {
        int k2 = i >> 6, r = i & 63;
        const float* Wr = (r < 32) ? (wqh + r * 64) : (wql + (r - 32) * 64);
        sWq[k2 * 64 + r] = pk2(Wr[2 * k2], Wr[2 * k2 + 1]);
    }
    if (tid < 32) sbq[tid] = bqh[tid];
    else if (tid < 64) sbq[tid] = bql[tid - 32];
    else if (tid < 128) sbo[tid - 64] = bo[tid - 64];

    // GEMM coords: 8 rows x 2 px; rG warp-uniform
    const int rG = (tid >> 5) * 8;           // 0,8,...,56
    const int pg = tid & 31;                 // px = 2*pg, 2*pg+1

    int bprev = -1;

    for (int t = t0; t < t1; ++t) {
        const int b = t / TPBATCH;
        if (b != bprev) {
            __syncthreads();   // prior GEMM2/norm readers of sW2/sks2 done
            const u64* gW2 = (const u64*)g_W2 + (size_t)b * 2048;
            for (int i = tid; i < 2048; i += TPB) sW2[i] = gW2[i];
            if (tid < 32)
                sks2[tid] = pk2(g_ksum[b * 64 + 2 * tid], g_ksum[b * 64 + 2 * tid + 1]);
            bprev = b;
        }
        const int n0 = (t % TPBATCH) * TILE;
        const float* xh = high + ((size_t)b * 64) * Np + n0;
        const float* xl = low  + ((size_t)b * 64) * Np + n0;

        __syncthreads();
#pragma unroll
        for (int it = 0; it < 8; it++) {
            int idx = tid + TPB * it;          // 0..2047
            int k2 = idx >> 6, px = idx & 63;
            sXh[k2 * XP + px] =
                pk2(xh[(size_t)(2 * k2) * Np + px], xh[(size_t)(2 * k2 + 1) * Np + px]);
            sXl[k2 * XP + px] =
                pk2(xl[(size_t)(2 * k2) * Np + px], xl[(size_t)(2 * k2 + 1) * Np + px]);
        }
        __syncthreads();

        // ---- GEMM1: q = softplus(Wq @ X) -> sQ packed ----
        {
            const u64* sXin = (rG < 32) ? sXh : sXl;
            u64 acc[16];
#pragma unroll
            for (int i = 0; i < 16; i++) acc[i] = 0ull;
#pragma unroll 4
            for (int k2 = 0; k2 < 32; k2++) {
                const ulonglong2* wp = (const ulonglong2*)(sWq + k2 * 64 + rG);
                ulonglong2 w01 = wp[0], w23 = wp[1], w45 = wp[2], w67 = wp[3];
                u64 w2r[8] = {w01.x, w01.y, w23.x, w23.y, w45.x, w45.y, w67.x, w67.y};
                ulonglong2 xa = *(const ulonglong2*)(sXin + k2 * XP + 2 * pg);
#pragma unroll
                for (int oi = 0; oi < 8; oi++) {
                    acc[oi * 2 + 0] = ffma2(w2r[oi], xa.x, acc[oi * 2 + 0]);
                    acc[oi * 2 + 1] = ffma2(w2r[oi], xa.y, acc[oi * 2 + 1]);
                }
            }
            // epilogue: bias + softplus, pack row-pairs into sQ
#pragma unroll
            for (int oi2 = 0; oi2 < 4; oi2++) {
                const int ra = rG + 2 * oi2;
                const float ba0 = sbq[ra], ba1 = sbq[ra + 1];
                float lo, hi;
                upk2(acc[(2 * oi2) * 2 + 0], lo, hi);     float v00 = softplus(lo + hi + ba0);
                upk2(acc[(2 * oi2) * 2 + 1], lo, hi);     float v01 = softplus(lo + hi + ba0);
                upk2(acc[(2 * oi2 + 1) * 2 + 0], lo, hi); float v10 = softplus(lo + hi + ba1);
                upk2(acc[(2 * oi2 + 1) * 2 + 1], lo, hi); float v11 = softplus(lo + hi + ba1);
                ulonglong2 st;
                st.x = pk2(v00, v10);
                st.y = pk2(v01, v11);
                *(ulonglong2*)(sQ + (ra >> 1) * XP + 2 * pg) = st;
            }
        }
        __syncthreads();

        // ---- fused norm + in-place rescale (all 256 threads) ----
#pragma unroll
        for (int rr = 0; rr < 2; rr++) {
            int it = tid + TPB * rr;           // 0..511
            int h = it >> 6, px = it & 63;
            u64 q0 = sQ[(h * 4 + 0) * XP + px];
            u64 q1 = sQ[(h * 4 + 1) * XP + px];
            u64 q2 = sQ[(h * 4 + 2) * XP + px];
            u64 q3 = sQ[(h * 4 + 3) * XP + px];
            u64 a = ffma2(q0, sks2[h * 4 + 0], 0ull);
            a = ffma2(q1, sks2[h * 4 + 1], a);
            a = ffma2(q2, sks2[h * 4 + 2], a);
            a = ffma2(q3, sks2[h * 4 + 3], a);
            float lo, hi; upk2(a, lo, hi);
            float inv = 1.0f / (lo + hi);
            u64 iv = pk2(inv, inv);
            sQ[(h * 4 + 0) * XP + px] = fmul2(q0, iv);
            sQ[(h * 4 + 1) * XP + px] = fmul2(q1, iv);
            sQ[(h * 4 + 2) * XP + px] = fmul2(q2, iv);
            sQ[(h * 4 + 3) * XP + px] = fmul2(q3, iv);
        }
        __syncthreads();

        // ---- GEMM2: out = W2 @ q' + bo ----
        {
            u64 acc[16];
#pragma unroll
            for (int i = 0; i < 16; i++) acc[i] = 0ull;
#pragma unroll 4
            for (int k2 = 0; k2 < 32; k2++) {
                const ulonglong2* wp = (const ulonglong2*)(sW2 + k2 * 64 + rG);
                ulonglong2 w01 = wp[0], w23 = wp[1], w45 = wp[2], w67 = wp[3];
                u64 w2r[8] = {w01.x, w01.y, w23.x, w23.y, w45.x, w45.y, w67.x, w67.y};
                ulonglong2 xa = *(const ulonglong2*)(sQ + k2 * XP + 2 * pg);
#pragma unroll
                for (int oi = 0; oi < 8; oi++) {
                    acc[oi * 2 + 0] = ffma2(w2r[oi], xa.x, acc[oi * 2 + 0]);
                    acc[oi * 2 + 1] = ffma2(w2r[oi], xa.y, acc[oi * 2 + 1]);
                }
            }
            float* ob = out + ((size_t)b * 64) * Np + n0;
#pragma unroll
            for (int oi = 0; oi < 8; oi++) {
                const int r = rG + oi;
                const float bias = sbo[r];
                float lo0, hi0, lo1, hi1;
                upk2(acc[oi * 2 + 0], lo0, hi0);
                upk2(acc[oi * 2 + 1], lo1, hi1);
                *(float2*)(ob + (size_t)r * Np + 2 * pg) =
                    make_float2(lo0 + hi0 + bias, lo1 + hi1 + bias);
            }
        }
    }
}

constexpr int SMEM1 = (4096 + 2 * 2112) * 8 + (128 * KP + 128) * 4;   // 101,888
constexpr int SMEM2 = (4096 + 3 * 2112 + 32) * 8 + 128 * 4;           // 84,224

}  // namespace mca

// ---------------------------------------------------------------------------
extern "C" void kernel_launch(void* const* d_in, const int* in_sizes, int n_in,
                              void* d_out, int out_size) {
    using namespace mca;
    (void)in_sizes; (void)n_in; (void)out_size;

    const float* high = (const float*)d_in[0];
    const float* low  = (const float*)d_in[1];
    const float* wqh  = (const float*)d_in[2];
    const float* bqh  = (const float*)d_in[3];
    const float* wql  = (const float*)d_in[4];
    const float* bql  = (const float*)d_in[5];
    const float* wk   = (const float*)d_in[6];
    const float* bk   = (const float*)d_in[7];
    const float* wv   = (const float*)d_in[8];
    const float* bv   = (const float*)d_in[9];
    const float* wo   = (const float*)d_in[10];
    const float* bo   = (const float*)d_in[11];
    float* out = (float*)d_out;

    cudaFuncSetAttribute(pass1, cudaFuncAttributeMaxDynamicSharedMemorySize, SMEM1);
    cudaFuncSetAttribute(pass2, cudaFuncAttributeMaxDynamicSharedMemorySize, SMEM2);

    zero_scratch<<<8, 512>>>();
    pass1<<<GRID, TPB, SMEM1>>>(low, wk, bk, wv, bv);
    prep<<<Bn, 512>>>(wo);
    pass2<<<GRID, TPB, SMEM2>>>(high, low, wqh, bqh, wql, bql, bo, out);
}